// round 8
// baseline (speedup 1.0000x reference)
#include <cuda_runtime.h>
#include <cuda_bf16.h>
#include <cstdint>

// ===================== problem constants =====================
#define BATCH 1024
#define EMB 512
#define NCLS 200000
#define NT 128                   // classes per CTA tile
#define NTILES 1563              // ceil(NCLS / NT)
#define CPAD (NTILES * NT)       // 200064
#define TILE_BYTES 65536         // 128 rows x 512 k x 1B (int8 tile)
#define CHUNK_BYTES 32768        // 128 rows x 256 k int8 (pipeline chunk)
#define NCHUNKS 16               // 8 m-tiles x 2 chunks
#define SCALE_S 64.0f
#define COS_M 0.877582561890373f
#define SIN_M 0.479425538604203f

// ===================== device scratch =====================
__device__ __align__(1024) unsigned char g_W[(size_t)NTILES * TILE_BYTES]; // ~100 MB int8 tiled
__device__ __align__(1024) unsigned char g_A[8 * TILE_BYTES];              // 512 KB int8 tiled
__device__ float g_winv[CPAD];    // per-class dequant factor
__device__ float g_ainv[BATCH];   // per-row dequant factor
__device__ float g_rowsum[BATCH];
__device__ float g_target[BATCH];
__device__ int   g_labels[BATCH];

#define DEVINL __device__ __forceinline__

// ===================== PTX helpers =====================
DEVINL uint32_t smem_u32(const void* p) {
    uint32_t a;
    asm("{ .reg .u64 t; cvta.to.shared.u64 t, %1; cvt.u32.u64 %0, t; }" : "=r"(a) : "l"(p));
    return a;
}

#define MBARRIER_INIT(addr, cnt) \
    asm volatile("mbarrier.init.shared.b64 [%0], %1;" :: "r"((uint32_t)(addr)), "r"((uint32_t)(cnt)) : "memory")

#define MBARRIER_EXPECT_TX(addr, bytes) \
    asm volatile("mbarrier.arrive.expect_tx.shared.b64 _, [%0], %1;" :: "r"((uint32_t)(addr)), "r"((uint32_t)(bytes)) : "memory")

#define MBARRIER_ARRIVE(addr) \
    asm volatile("mbarrier.arrive.shared.b64 _, [%0];" :: "r"((uint32_t)(addr)) : "memory")

#define MBARRIER_WAIT_PARITY(addr, parity) do {                                   \
    asm volatile(                                                                 \
        "{\n\t.reg .pred P1;\n\t"                                                 \
        "WAIT_LOOP_%=:\n\t"                                                       \
        "mbarrier.try_wait.parity.acquire.cta.shared::cta.b64 P1, [%0], %1, 0x989680;\n\t" \
        "@P1 bra.uni WAIT_DONE_%=;\n\t"                                           \
        "bra.uni WAIT_LOOP_%=;\n\t"                                               \
        "WAIT_DONE_%=:\n\t}"                                                      \
        :: "r"((uint32_t)(addr)), "r"((uint32_t)(parity)) : "memory");            \
} while (0)

#define MBAR_INVAL(addr) \
    asm volatile("mbarrier.inval.shared.b64 [%0];" :: "r"((uint32_t)(addr)) : "memory")

#define BULK_G2S(dst_smem, src_gmem, bytes, mbar)                                                   \
    asm volatile("cp.async.bulk.shared::cluster.global.mbarrier::complete_tx::bytes [%0], [%1], %2, [%3];" \
        :: "r"((uint32_t)(dst_smem)), "l"(src_gmem), "r"((uint32_t)(bytes)), "r"((uint32_t)(mbar)) : "memory")

DEVINL void ldsm_x4(uint32_t* r, uint32_t addr) {
    asm volatile("ldmatrix.sync.aligned.m8n8.x4.shared.b16 {%0,%1,%2,%3}, [%4];"
                 : "=r"(r[0]), "=r"(r[1]), "=r"(r[2]), "=r"(r[3]) : "r"(addr));
}

// int8 MMA: m16n8k32, s32 accumulate (exact)
DEVINL void mma_s8(int* c, const uint32_t* a, uint32_t b0, uint32_t b1) {
    asm volatile(
        "mma.sync.aligned.m16n8k32.row.col.s32.s8.s8.s32 "
        "{%0,%1,%2,%3}, {%4,%5,%6,%7}, {%8,%9}, {%0,%1,%2,%3};"
        : "+r"(c[0]), "+r"(c[1]), "+r"(c[2]), "+r"(c[3])
        : "r"(a[0]), "r"(a[1]), "r"(a[2]), "r"(a[3]), "r"(b0), "r"(b1));
}

// int8 element (row, kbyte) inside a tiled region:
// [kbyte/128 superblock: 16KB][row/8 group: 1KB][SW128 atom: 8 rows x 128B]
DEVINL uint32_t sw8(uint32_t base, int row, int kb) {
    return base + (uint32_t)(((kb >> 7) << 14) + ((row >> 3) << 10) + ((row & 7) << 7)
                             + ((kb & 127) ^ ((row & 7) << 4)));
}

// ===================== prep: normalize + int8 quantize =====================
DEVINL float dot4(float4 v) { return v.x * v.x + v.y * v.y + v.z * v.z + v.w * v.w; }
DEVINL float max4(float4 v) {
    return fmaxf(fmaxf(fabsf(v.x), fabsf(v.y)), fmaxf(fabsf(v.z), fabsf(v.w)));
}
DEVINL uint32_t q4(float4 v, float qs) {
    int a = __float2int_rn(v.x * qs) & 255, b = __float2int_rn(v.y * qs) & 255;
    int c = __float2int_rn(v.z * qs) & 255, d = __float2int_rn(v.w * qs) & 255;
    return (uint32_t)(a | (b << 8) | (c << 16) | (d << 24));
}

// one warp handles one row: normalize, quantize to int8 tile layout, store inv factor
DEVINL void norm_row_q(const float* __restrict__ src, unsigned char* __restrict__ dstTile,
                       float* __restrict__ invp, int r, int rr, int nvalid) {
    int lane = threadIdx.x & 31;
    float4 x0, x1, x2, x3;
    if (r < nvalid) {
        const float4* s = reinterpret_cast<const float4*>(src + (size_t)r * EMB);
        x0 = s[2 * lane]; x1 = s[2 * lane + 1]; x2 = s[64 + 2 * lane]; x3 = s[65 + 2 * lane];
    } else {
        x0 = x1 = x2 = x3 = make_float4(0.f, 0.f, 0.f, 0.f);
    }
    float ss = dot4(x0) + dot4(x1) + dot4(x2) + dot4(x3);
    float am = fmaxf(fmaxf(max4(x0), max4(x1)), fmaxf(max4(x2), max4(x3)));
    #pragma unroll
    for (int o = 16; o; o >>= 1) {
        ss += __shfl_xor_sync(0xFFFFFFFFu, ss, o);
        am = fmaxf(am, __shfl_xor_sync(0xFFFFFFFFu, am, o));
    }
    float inv = 1.0f / fmaxf(sqrtf(ss), 1e-12f);
    float amaxn = am * inv;                       // max |normalized element|
    float qs = 127.0f * inv / fmaxf(amaxn, 1e-30f); // x * qs = vn * 127/amaxn
    if (lane == 0) invp[r < nvalid ? r : r] = amaxn * (1.0f / 127.0f);
    uint2 w0, w1;
    w0.x = q4(x0, qs); w0.y = q4(x1, qs);
    w1.x = q4(x2, qs); w1.y = q4(x3, qs);
    // kbytes 8*lane and 256+8*lane; 8B writes stay contiguous under 16B-unit swizzle
    *reinterpret_cast<uint2*>(dstTile + (sw8(0, rr, 8 * lane)))       = w0;
    *reinterpret_cast<uint2*>(dstTile + (sw8(0, rr, 256 + 8 * lane))) = w1;
}

__global__ void k_prep_a(const float* __restrict__ emb) {
    int r = blockIdx.x * 8 + (threadIdx.x >> 5);
    norm_row_q(emb, g_A + (size_t)(r >> 7) * TILE_BYTES, g_ainv, r, r & 127, BATCH);
}

__global__ void k_prep_w(const float* __restrict__ w) {
    int r = blockIdx.x * 8 + (threadIdx.x >> 5);
    norm_row_q(w, g_W + (size_t)(r >> 7) * TILE_BYTES, g_winv, r, r & 127, NCLS);
}

// labels: detect int64 vs int32 (odd 32-bit words all zero => int64), zero rowsum
__global__ void k_labels(const int* __restrict__ lw) {
    __shared__ int s64;
    int tid = threadIdx.x;
    if (tid == 0) s64 = 1;
    __syncthreads();
    if (tid < 64) {
        if (lw[2 * tid + 1] != 0) atomicExch(&s64, 0);
    }
    __syncthreads();
    int is64 = s64;
    for (int i = tid; i < BATCH; i += 256) {
        g_labels[i] = is64 ? lw[2 * i] : lw[i];
        g_rowsum[i] = 0.0f;
    }
}

// exact fp32 target logit per row: margined, added to rowsum (GEMM skips label col)
__global__ void k_fix(const float* __restrict__ emb, const float* __restrict__ w) {
    int wrp = (blockIdx.x * blockDim.x + threadIdx.x) >> 5;   // 0..1023
    int lane = threadIdx.x & 31;
    int lbl = g_labels[wrp];
    const float4* e4 = reinterpret_cast<const float4*>(emb + (size_t)wrp * EMB);
    const float4* w4 = reinterpret_cast<const float4*>(w + (size_t)lbl * EMB);
    float ee = 0.f, ww = 0.f, ew = 0.f;
    #pragma unroll
    for (int i = 0; i < 4; i++) {
        float4 a = e4[lane + 32 * i], b = w4[lane + 32 * i];
        ee += dot4(a); ww += dot4(b);
        ew += a.x * b.x + a.y * b.y + a.z * b.z + a.w * b.w;
    }
    #pragma unroll
    for (int o = 16; o; o >>= 1) {
        ee += __shfl_xor_sync(0xFFFFFFFFu, ee, o);
        ww += __shfl_xor_sync(0xFFFFFFFFu, ww, o);
        ew += __shfl_xor_sync(0xFFFFFFFFu, ew, o);
    }
    if (lane == 0) {
        float t = ew / (fmaxf(sqrtf(ee), 1e-12f) * fmaxf(sqrtf(ww), 1e-12f));
        t = fminf(fmaxf(t, -1.0f), 1.0f);
        t = fminf(fmaxf(t, -1.0f + 1e-7f), 1.0f - 1e-7f);
        float lg = (t * COS_M - sqrtf(fmaxf(1.0f - t * t, 0.0f)) * SIN_M) * SCALE_S;
        g_target[wrp] = lg;
        atomicAdd(&g_rowsum[wrp], __expf(lg - 64.0f));
    }
}

// ===================== int8 GEMM + fused softmax-partial epilogue =====================
// 288 threads: warps 0-7 compute (4 m-slices x 2 n-slices, warp tile 32x64, k-step 32),
// warp 8 = loader. B tile (128 classes x 512 k int8 = 64 KB) SMEM-resident.
__global__ __launch_bounds__(288, 1) void k_gemm() {
    extern __shared__ unsigned char smem[];
    uint32_t sb = smem_u32(smem);
    int tid = threadIdx.x, wid = tid >> 5, lane = tid & 31;

    const uint32_t MB_B  = sb + 16;
    const uint32_t MB_AL = sb + 32;   // full barriers [2]
    const uint32_t MB_AC = sb + 64;   // consumed barriers [2]
    const uint32_t A_OFF = 1024;      // 2 x 32KB chunk buffers
    const uint32_t B_OFF = 66560;     // + 64KB => 132096 total

    if (tid == 0) {
        MBARRIER_INIT(MB_B, 1);
        for (int i = 0; i < 2; i++) {
            MBARRIER_INIT(MB_AL + 16 * i, 1);
            MBARRIER_INIT(MB_AC + 16 * i, 8);
        }
    }
    __syncthreads();

    if (wid == 8) {
        if (lane == 0) {
            MBARRIER_EXPECT_TX(MB_B, TILE_BYTES);
            BULK_G2S(sb + B_OFF, g_W + (size_t)blockIdx.x * TILE_BYTES, TILE_BYTES, MB_B);
            #pragma unroll
            for (int g = 0; g < 2; g++) {
                MBARRIER_EXPECT_TX(MB_AL + 16 * g, CHUNK_BYTES);
                BULK_G2S(sb + A_OFF + g * CHUNK_BYTES, g_A + (size_t)g * CHUNK_BYTES,
                         CHUNK_BYTES, MB_AL + 16 * g);
            }
            int ac_ph[2] = {0, 0};
            for (int g = 2; g < NCHUNKS; g++) {
                int buf = g & 1;
                MBARRIER_WAIT_PARITY(MB_AC + 16 * buf, ac_ph[buf]); ac_ph[buf] ^= 1;
                MBARRIER_EXPECT_TX(MB_AL + 16 * buf, CHUNK_BYTES);
                BULK_G2S(sb + A_OFF + buf * CHUNK_BYTES, g_A + (size_t)g * CHUNK_BYTES,
                         CHUNK_BYTES, MB_AL + 16 * buf);
            }
        }
    } else {
        int wm = wid & 3, wn = wid >> 2;                 // 4 m-slices x 2 n-slices
        int grp = lane >> 3, r8 = lane & 7;
        int a_row = wm * 32 + ((grp & 1) << 3) + r8;
        int a_kb  = (grp >> 1) << 4;                     // byte offset 0 / 16
        int b_n   = wn * 64 + ((grp >> 1) << 3) + r8;
        int b_kb  = (grp & 1) << 4;
        int qr = lane >> 2, ql = lane & 3;
        int cbase = blockIdx.x * NT + wn * 64 + ql * 2;

        // preload per-column dequant factors (16 columns per thread)
        float wv[16];
        #pragma unroll
        for (int j = 0; j < 8; j++) {
            wv[j * 2]     = g_winv[cbase + j * 8];
            wv[j * 2 + 1] = g_winv[cbase + j * 8 + 1];
        }

        MBARRIER_WAIT_PARITY(MB_B, 0);

        int al_ph[2] = {0, 0};
        #pragma unroll 1
        for (int m = 0; m < 8; m++) {
            int acc[2][8][4];
            #pragma unroll
            for (int i = 0; i < 2; i++)
                #pragma unroll
                for (int j = 0; j < 8; j++)
                    #pragma unroll
                    for (int e = 0; e < 4; e++) acc[i][j][e] = 0;

            #pragma unroll 1
            for (int kc = 0; kc < 2; kc++) {
                int g = m * 2 + kc, buf = g & 1;
                MBARRIER_WAIT_PARITY(MB_AL + 16 * buf, al_ph[buf]); al_ph[buf] ^= 1;
                uint32_t abuf = sb + A_OFF + buf * CHUNK_BYTES;
                #pragma unroll
                for (int ks = 0; ks < 8; ks++) {
                    int kb = ks * 32;
                    uint32_t a[2][4], b[4][4];
                    ldsm_x4(a[0], sw8(abuf, a_row,      kb + a_kb));
                    ldsm_x4(a[1], sw8(abuf, a_row + 16, kb + a_kb));
                    #pragma unroll
                    for (int jj = 0; jj < 4; jj++)
                        ldsm_x4(b[jj], sw8(sb + B_OFF, b_n + jj * 16, kc * 256 + kb + b_kb));
                    if (ks == 7 && lane == 0) MBARRIER_ARRIVE(MB_AC + 16 * buf);
                    #pragma unroll
                    for (int i = 0; i < 2; i++)
                        #pragma unroll
                        for (int j = 0; j < 8; j++)
                            mma_s8(acc[i][j], a[i],
                                   b[j >> 1][(j & 1) * 2], b[j >> 1][(j & 1) * 2 + 1]);
                }
            }

            // fused epilogue: dequant, clamp, softmax partial (label skipped -> k_fix)
            #pragma unroll
            for (int i = 0; i < 2; i++) {
                #pragma unroll
                for (int h = 0; h < 2; h++) {
                    int R = m * 128 + wm * 32 + i * 16 + h * 8 + qr;
                    int lbl = g_labels[R];
                    float af = g_ainv[R];
                    float sum = 0.0f;
                    #pragma unroll
                    for (int j = 0; j < 8; j++) {
                        #pragma unroll
                        for (int e = 0; e < 2; e++) {
                            int c = cbase + j * 8 + e;
                            float v = __int2float_rn(acc[i][j][h * 2 + e]) * (af * wv[j * 2 + e]);
                            v = fminf(fmaxf(v, -1.0f), 1.0f);
                            if (c != lbl && c < NCLS) sum += __expf(v * 64.0f - 64.0f);
                        }
                    }
                    sum += __shfl_xor_sync(0xFFFFFFFFu, sum, 1);
                    sum += __shfl_xor_sync(0xFFFFFFFFu, sum, 2);
                    if (ql == 0) atomicAdd(&g_rowsum[R], sum);
                }
            }
        }
    }

    __syncthreads();
    if (tid == 0) {
        MBAR_INVAL(MB_B);
        for (int i = 0; i < 2; i++) { MBAR_INVAL(MB_AL + 16 * i); MBAR_INVAL(MB_AC + 16 * i); }
    }
}

// ===================== final reduction =====================
__global__ void k_final(float* __restrict__ out) {
    __shared__ float sd[BATCH];
    int t = threadIdx.x;
    sd[t] = 64.0f + logf(g_rowsum[t]) - g_target[t];
    __syncthreads();
    for (int s = 512; s > 0; s >>= 1) {
        if (t < s) sd[t] += sd[t + s];
        __syncthreads();
    }
    if (t == 0) out[0] = sd[0] * (1.0f / (float)BATCH);
}

// ===================== launch =====================
extern "C" void kernel_launch(void* const* d_in, const int* in_sizes, int n_in,
                              void* d_out, int out_size) {
    const float* emb = (const float*)d_in[0];
    const float* w   = (const float*)d_in[1];
    const int*   lw  = (const int*)d_in[2];
    float* out = (float*)d_out;

    cudaFuncSetAttribute(k_gemm, cudaFuncAttributeMaxDynamicSharedMemorySize, 132096);

    k_labels<<<1, 256>>>(lw);
    k_prep_a<<<BATCH / 8, 256>>>(emb);
    k_prep_w<<<CPAD / 8, 256>>>(w);
    k_fix<<<BATCH / 8, 256>>>(emb, w);
    k_gemm<<<NTILES, 288, 132096>>>();
    k_final<<<1, BATCH>>>(out);
}

// round 9
// speedup vs baseline: 1.7019x; 1.7019x over previous
#include <cuda_runtime.h>
#include <cuda_bf16.h>
#include <cstdint>

// ===================== problem constants =====================
#define BATCH 1024
#define EMB 512
#define NCLS 200000
#define NT 128                   // classes per CTA tile
#define NTILES 1563              // ceil(NCLS / NT)
#define CPAD (NTILES * NT)       // 200064
#define TILE_BYTES 65536         // 128 rows x 512 k x 1B (fp8 tile)
#define CHUNK_BYTES 32768        // 128 rows x 256 k fp8 (pipeline chunk)
#define NCHUNKS 16               // 8 m-tiles x 2 chunks
#define SCALE_S 64.0f
#define COS_M 0.877582561890373f
#define SIN_M 0.479425538604203f
#define FP8_MAX 448.0f

// ===================== device scratch =====================
__device__ __align__(1024) unsigned char g_W[(size_t)NTILES * TILE_BYTES]; // ~100 MB fp8 tiled
__device__ __align__(1024) unsigned char g_A[8 * TILE_BYTES];              // 512 KB fp8 tiled
__device__ float g_winv[CPAD];    // per-class dequant factor
__device__ float g_ainv[BATCH];   // per-row dequant factor
__device__ float g_rowsum[BATCH];
__device__ float g_target[BATCH];
__device__ int   g_labels[BATCH];

#define DEVINL __device__ __forceinline__

// ===================== PTX helpers =====================
DEVINL uint32_t smem_u32(const void* p) {
    uint32_t a;
    asm("{ .reg .u64 t; cvta.to.shared.u64 t, %1; cvt.u32.u64 %0, t; }" : "=r"(a) : "l"(p));
    return a;
}

#define MBARRIER_INIT(addr, cnt) \
    asm volatile("mbarrier.init.shared.b64 [%0], %1;" :: "r"((uint32_t)(addr)), "r"((uint32_t)(cnt)) : "memory")

#define MBARRIER_EXPECT_TX(addr, bytes) \
    asm volatile("mbarrier.arrive.expect_tx.shared.b64 _, [%0], %1;" :: "r"((uint32_t)(addr)), "r"((uint32_t)(bytes)) : "memory")

#define MBARRIER_ARRIVE(addr) \
    asm volatile("mbarrier.arrive.shared.b64 _, [%0];" :: "r"((uint32_t)(addr)) : "memory")

#define MBARRIER_WAIT_PARITY(addr, parity) do {                                   \
    asm volatile(                                                                 \
        "{\n\t.reg .pred P1;\n\t"                                                 \
        "WAIT_LOOP_%=:\n\t"                                                       \
        "mbarrier.try_wait.parity.acquire.cta.shared::cta.b64 P1, [%0], %1, 0x989680;\n\t" \
        "@P1 bra.uni WAIT_DONE_%=;\n\t"                                           \
        "bra.uni WAIT_LOOP_%=;\n\t"                                               \
        "WAIT_DONE_%=:\n\t}"                                                      \
        :: "r"((uint32_t)(addr)), "r"((uint32_t)(parity)) : "memory");            \
} while (0)

#define MBAR_INVAL(addr) \
    asm volatile("mbarrier.inval.shared.b64 [%0];" :: "r"((uint32_t)(addr)) : "memory")

#define BULK_G2S(dst_smem, src_gmem, bytes, mbar)                                                   \
    asm volatile("cp.async.bulk.shared::cluster.global.mbarrier::complete_tx::bytes [%0], [%1], %2, [%3];" \
        :: "r"((uint32_t)(dst_smem)), "l"(src_gmem), "r"((uint32_t)(bytes)), "r"((uint32_t)(mbar)) : "memory")

DEVINL void ldsm_x4(uint32_t* r, uint32_t addr) {
    asm volatile("ldmatrix.sync.aligned.m8n8.x4.shared.b16 {%0,%1,%2,%3}, [%4];"
                 : "=r"(r[0]), "=r"(r[1]), "=r"(r[2]), "=r"(r[3]) : "r"(addr));
}

// fp8 MMA: m16n8k32 e4m3 x e4m3 -> f32
DEVINL void mma_f8(float* c, const uint32_t* a, uint32_t b0, uint32_t b1) {
    asm volatile(
        "mma.sync.aligned.m16n8k32.row.col.f32.e4m3.e4m3.f32 "
        "{%0,%1,%2,%3}, {%4,%5,%6,%7}, {%8,%9}, {%0,%1,%2,%3};"
        : "+f"(c[0]), "+f"(c[1]), "+f"(c[2]), "+f"(c[3])
        : "r"(a[0]), "r"(a[1]), "r"(a[2]), "r"(a[3]), "r"(b0), "r"(b1));
}

// fp8 element (row, kbyte) inside a tiled region:
// [kbyte/128 superblock: 16KB][row/8 group: 1KB][SW128 atom: 8 rows x 128B]
DEVINL uint32_t sw8(uint32_t base, int row, int kb) {
    return base + (uint32_t)(((kb >> 7) << 14) + ((row >> 3) << 10) + ((row & 7) << 7)
                             + ((kb & 127) ^ ((row & 7) << 4)));
}

// ===================== prep: normalize + fp8 quantize =====================
DEVINL float dot4(float4 v) { return v.x * v.x + v.y * v.y + v.z * v.z + v.w * v.w; }
DEVINL float max4(float4 v) {
    return fmaxf(fmaxf(fabsf(v.x), fabsf(v.y)), fmaxf(fabsf(v.z), fabsf(v.w)));
}
// pack 4 scaled floats into 4 e4m3 bytes (v0 lowest byte)
DEVINL uint32_t qf8(float4 v, float qs) {
    uint32_t out;
    asm("{ .reg .b16 lo, hi;\n\t"
        "cvt.rn.satfinite.e4m3x2.f32 lo, %2, %1;\n\t"
        "cvt.rn.satfinite.e4m3x2.f32 hi, %4, %3;\n\t"
        "mov.b32 %0, {lo, hi}; }"
        : "=r"(out)
        : "f"(v.x * qs), "f"(v.y * qs), "f"(v.z * qs), "f"(v.w * qs));
    return out;
}

// one warp handles one row: normalize, fp8-quantize into tile layout, store inv factor
DEVINL void norm_row_q(const float* __restrict__ src, unsigned char* __restrict__ dstTile,
                       float* __restrict__ invp, int r, int rr, int nvalid) {
    int lane = threadIdx.x & 31;
    float4 x0, x1, x2, x3;
    if (r < nvalid) {
        const float4* s = reinterpret_cast<const float4*>(src + (size_t)r * EMB);
        x0 = s[2 * lane]; x1 = s[2 * lane + 1]; x2 = s[64 + 2 * lane]; x3 = s[65 + 2 * lane];
    } else {
        x0 = x1 = x2 = x3 = make_float4(0.f, 0.f, 0.f, 0.f);
    }
    float ss = dot4(x0) + dot4(x1) + dot4(x2) + dot4(x3);
    float am = fmaxf(fmaxf(max4(x0), max4(x1)), fmaxf(max4(x2), max4(x3)));
    #pragma unroll
    for (int o = 16; o; o >>= 1) {
        ss += __shfl_xor_sync(0xFFFFFFFFu, ss, o);
        am = fmaxf(am, __shfl_xor_sync(0xFFFFFFFFu, am, o));
    }
    float inv = 1.0f / fmaxf(sqrtf(ss), 1e-12f);
    float amaxn = fmaxf(am * inv, 1e-30f);        // max |normalized element|
    float qs = FP8_MAX * inv / amaxn;             // x*qs = vn * 448/amaxn  (amax -> 448)
    if (lane == 0) invp[r] = amaxn * (1.0f / FP8_MAX);
    uint2 w0, w1;
    w0.x = qf8(x0, qs); w0.y = qf8(x1, qs);
    w1.x = qf8(x2, qs); w1.y = qf8(x3, qs);
    // kbytes 8*lane and 256+8*lane; 8B writes stay contiguous under 16B-unit swizzle
    *reinterpret_cast<uint2*>(dstTile + (sw8(0, rr, 8 * lane)))       = w0;
    *reinterpret_cast<uint2*>(dstTile + (sw8(0, rr, 256 + 8 * lane))) = w1;
}

__global__ void k_prep_a(const float* __restrict__ emb) {
    int r = blockIdx.x * 8 + (threadIdx.x >> 5);
    norm_row_q(emb, g_A + (size_t)(r >> 7) * TILE_BYTES, g_ainv, r, r & 127, BATCH);
}

__global__ void k_prep_w(const float* __restrict__ w) {
    int r = blockIdx.x * 8 + (threadIdx.x >> 5);
    norm_row_q(w, g_W + (size_t)(r >> 7) * TILE_BYTES, g_winv, r, r & 127, NCLS);
}

// labels: detect int64 vs int32 (odd 32-bit words all zero => int64), zero rowsum
__global__ void k_labels(const int* __restrict__ lw) {
    __shared__ int s64;
    int tid = threadIdx.x;
    if (tid == 0) s64 = 1;
    __syncthreads();
    if (tid < 64) {
        if (lw[2 * tid + 1] != 0) atomicExch(&s64, 0);
    }
    __syncthreads();
    int is64 = s64;
    for (int i = tid; i < BATCH; i += 256) {
        g_labels[i] = is64 ? lw[2 * i] : lw[i];
        g_rowsum[i] = 0.0f;
    }
}

// exact fp32 target logit per row: margined, added to rowsum (GEMM skips label col)
__global__ void k_fix(const float* __restrict__ emb, const float* __restrict__ w) {
    int wrp = (blockIdx.x * blockDim.x + threadIdx.x) >> 5;   // 0..1023
    int lane = threadIdx.x & 31;
    int lbl = g_labels[wrp];
    const float4* e4 = reinterpret_cast<const float4*>(emb + (size_t)wrp * EMB);
    const float4* w4 = reinterpret_cast<const float4*>(w + (size_t)lbl * EMB);
    float ee = 0.f, ww = 0.f, ew = 0.f;
    #pragma unroll
    for (int i = 0; i < 4; i++) {
        float4 a = e4[lane + 32 * i], b = w4[lane + 32 * i];
        ee += dot4(a); ww += dot4(b);
        ew += a.x * b.x + a.y * b.y + a.z * b.z + a.w * b.w;
    }
    #pragma unroll
    for (int o = 16; o; o >>= 1) {
        ee += __shfl_xor_sync(0xFFFFFFFFu, ee, o);
        ww += __shfl_xor_sync(0xFFFFFFFFu, ww, o);
        ew += __shfl_xor_sync(0xFFFFFFFFu, ew, o);
    }
    if (lane == 0) {
        float t = ew / (fmaxf(sqrtf(ee), 1e-12f) * fmaxf(sqrtf(ww), 1e-12f));
        t = fminf(fmaxf(t, -1.0f), 1.0f);
        t = fminf(fmaxf(t, -1.0f + 1e-7f), 1.0f - 1e-7f);
        float lg = (t * COS_M - sqrtf(fmaxf(1.0f - t * t, 0.0f)) * SIN_M) * SCALE_S;
        g_target[wrp] = lg;
        atomicAdd(&g_rowsum[wrp], __expf(lg - 64.0f));
    }
}

// ===================== fp8 GEMM + fused softmax-partial epilogue =====================
// 288 threads: warps 0-7 compute (4 m-slices x 2 n-slices, warp tile 32x64, k-step 32),
// warp 8 = loader. B tile (128 classes x 512 k fp8 = 64 KB) SMEM-resident.
__global__ __launch_bounds__(288, 1) void k_gemm() {
    extern __shared__ unsigned char smem[];
    uint32_t sb = smem_u32(smem);
    int tid = threadIdx.x, wid = tid >> 5, lane = tid & 31;

    const uint32_t MB_B  = sb + 16;
    const uint32_t MB_AL = sb + 32;   // full barriers [2]
    const uint32_t MB_AC = sb + 64;   // consumed barriers [2]
    const uint32_t A_OFF = 1024;      // 2 x 32KB chunk buffers
    const uint32_t B_OFF = 66560;     // + 64KB => 132096 total

    if (tid == 0) {
        MBARRIER_INIT(MB_B, 1);
        for (int i = 0; i < 2; i++) {
            MBARRIER_INIT(MB_AL + 16 * i, 1);
            MBARRIER_INIT(MB_AC + 16 * i, 8);
        }
    }
    __syncthreads();

    if (wid == 8) {
        if (lane == 0) {
            MBARRIER_EXPECT_TX(MB_B, TILE_BYTES);
            BULK_G2S(sb + B_OFF, g_W + (size_t)blockIdx.x * TILE_BYTES, TILE_BYTES, MB_B);
            #pragma unroll
            for (int g = 0; g < 2; g++) {
                MBARRIER_EXPECT_TX(MB_AL + 16 * g, CHUNK_BYTES);
                BULK_G2S(sb + A_OFF + g * CHUNK_BYTES, g_A + (size_t)g * CHUNK_BYTES,
                         CHUNK_BYTES, MB_AL + 16 * g);
            }
            int ac_ph[2] = {0, 0};
            for (int g = 2; g < NCHUNKS; g++) {
                int buf = g & 1;
                MBARRIER_WAIT_PARITY(MB_AC + 16 * buf, ac_ph[buf]); ac_ph[buf] ^= 1;
                MBARRIER_EXPECT_TX(MB_AL + 16 * buf, CHUNK_BYTES);
                BULK_G2S(sb + A_OFF + buf * CHUNK_BYTES, g_A + (size_t)g * CHUNK_BYTES,
                         CHUNK_BYTES, MB_AL + 16 * buf);
            }
        }
    } else {
        int wm = wid & 3, wn = wid >> 2;                 // 4 m-slices x 2 n-slices
        int grp = lane >> 3, r8 = lane & 7;
        int a_row = wm * 32 + ((grp & 1) << 3) + r8;
        int a_kb  = (grp >> 1) << 4;                     // byte offset 0 / 16
        int b_n   = wn * 64 + ((grp >> 1) << 3) + r8;
        int b_kb  = (grp & 1) << 4;
        int qr = lane >> 2, ql = lane & 3;
        int cbase = blockIdx.x * NT + wn * 64 + ql * 2;

        // preload per-column dequant factors (16 columns per thread)
        float wv[16];
        #pragma unroll
        for (int j = 0; j < 8; j++) {
            wv[j * 2]     = g_winv[cbase + j * 8];
            wv[j * 2 + 1] = g_winv[cbase + j * 8 + 1];
        }

        MBARRIER_WAIT_PARITY(MB_B, 0);

        int al_ph[2] = {0, 0};
        #pragma unroll 1
        for (int m = 0; m < 8; m++) {
            float acc[2][8][4];
            #pragma unroll
            for (int i = 0; i < 2; i++)
                #pragma unroll
                for (int j = 0; j < 8; j++)
                    #pragma unroll
                    for (int e = 0; e < 4; e++) acc[i][j][e] = 0.0f;

            #pragma unroll 1
            for (int kc = 0; kc < 2; kc++) {
                int g = m * 2 + kc, buf = g & 1;
                MBARRIER_WAIT_PARITY(MB_AL + 16 * buf, al_ph[buf]); al_ph[buf] ^= 1;
                uint32_t abuf = sb + A_OFF + buf * CHUNK_BYTES;
                #pragma unroll
                for (int ks = 0; ks < 8; ks++) {
                    int kb = ks * 32;
                    uint32_t a[2][4], b[4][4];
                    ldsm_x4(a[0], sw8(abuf, a_row,      kb + a_kb));
                    ldsm_x4(a[1], sw8(abuf, a_row + 16, kb + a_kb));
                    #pragma unroll
                    for (int jj = 0; jj < 4; jj++)
                        ldsm_x4(b[jj], sw8(sb + B_OFF, b_n + jj * 16, kc * 256 + kb + b_kb));
                    if (ks == 7 && lane == 0) MBARRIER_ARRIVE(MB_AC + 16 * buf);
                    #pragma unroll
                    for (int i = 0; i < 2; i++)
                        #pragma unroll
                        for (int j = 0; j < 8; j++)
                            mma_f8(acc[i][j], a[i],
                                   b[j >> 1][(j & 1) * 2], b[j >> 1][(j & 1) * 2 + 1]);
                }
            }

            // fused epilogue: dequant, clamp, softmax partial (label handled by k_fix)
            #pragma unroll
            for (int i = 0; i < 2; i++) {
                #pragma unroll
                for (int h = 0; h < 2; h++) {
                    int R = m * 128 + wm * 32 + i * 16 + h * 8 + qr;
                    int lbl = g_labels[R];
                    float af = g_ainv[R];
                    float sum = 0.0f;
                    #pragma unroll
                    for (int j = 0; j < 8; j++) {
                        #pragma unroll
                        for (int e = 0; e < 2; e++) {
                            int c = cbase + j * 8 + e;
                            float v = acc[i][j][h * 2 + e] * (af * wv[j * 2 + e]);
                            v = fminf(fmaxf(v, -1.0f), 1.0f);
                            if (c != lbl && c < NCLS) sum += __expf(v * 64.0f - 64.0f);
                        }
                    }
                    sum += __shfl_xor_sync(0xFFFFFFFFu, sum, 1);
                    sum += __shfl_xor_sync(0xFFFFFFFFu, sum, 2);
                    if (ql == 0) atomicAdd(&g_rowsum[R], sum);
                }
            }
        }
    }

    __syncthreads();
    if (tid == 0) {
        MBAR_INVAL(MB_B);
        for (int i = 0; i < 2; i++) { MBAR_INVAL(MB_AL + 16 * i); MBAR_INVAL(MB_AC + 16 * i); }
    }
}

// ===================== final reduction =====================
__global__ void k_final(float* __restrict__ out) {
    __shared__ float sd[BATCH];
    int t = threadIdx.x;
    sd[t] = 64.0f + logf(g_rowsum[t]) - g_target[t];
    __syncthreads();
    for (int s = 512; s > 0; s >>= 1) {
        if (t < s) sd[t] += sd[t + s];
        __syncthreads();
    }
    if (t == 0) out[0] = sd[0] * (1.0f / (float)BATCH);
}

// ===================== launch =====================
extern "C" void kernel_launch(void* const* d_in, const int* in_sizes, int n_in,
                              void* d_out, int out_size) {
    const float* emb = (const float*)d_in[0];
    const float* w   = (const float*)d_in[1];
    const int*   lw  = (const int*)d_in[2];
    float* out = (float*)d_out;

    cudaFuncSetAttribute(k_gemm, cudaFuncAttributeMaxDynamicSharedMemorySize, 132096);

    k_labels<<<1, 256>>>(lw);
    k_prep_a<<<BATCH / 8, 256>>>(emb);
    k_prep_w<<<CPAD / 8, 256>>>(w);
    k_fix<<<BATCH / 8, 256>>>(emb, w);
    k_gemm<<<NTILES, 288, 132096>>>();
    k_final<<<1, BATCH>>>(out);
}

// round 10
// speedup vs baseline: 2.6267x; 1.5434x over previous
#include <cuda_runtime.h>
#include <cuda_fp16.h>
#include <cstdint>

// ===================== problem constants =====================
#define BATCH 1024
#define EMB 512
#define NCLS 200000
#define NT 128                   // classes per CTA tile
#define NTILES 1563              // ceil(NCLS / NT)
#define TILE_BYTES 131072        // 128 rows x 512 k x 2B (fp16 tile)
#define CHUNK_BYTES 32768        // 128 rows x 128 k fp16 (pipeline chunk)
#define NCHUNKS 32               // 8 m-tiles x 4 chunks
#define SCALE_S 64.0f
#define COS_M 0.877582561890373f
#define SIN_M 0.479425538604203f
#define K_LOG2E 92.332482616893657f   // 64 * log2(e)

// ===================== device scratch =====================
__device__ __align__(1024) unsigned char g_A[8 * TILE_BYTES];  // 1 MB fp16 tiled embeddings
__device__ float g_rowsum[BATCH];
__device__ float g_target[BATCH];
__device__ int   g_labels[BATCH];

#define DEVINL __device__ __forceinline__

// ===================== PTX helpers =====================
DEVINL uint32_t smem_u32(const void* p) {
    uint32_t a;
    asm("{ .reg .u64 t; cvta.to.shared.u64 t, %1; cvt.u32.u64 %0, t; }" : "=r"(a) : "l"(p));
    return a;
}

#define MBARRIER_INIT(addr, cnt) \
    asm volatile("mbarrier.init.shared.b64 [%0], %1;" :: "r"((uint32_t)(addr)), "r"((uint32_t)(cnt)) : "memory")

#define MBARRIER_EXPECT_TX(addr, bytes) \
    asm volatile("mbarrier.arrive.expect_tx.shared.b64 _, [%0], %1;" :: "r"((uint32_t)(addr)), "r"((uint32_t)(bytes)) : "memory")

#define MBARRIER_ARRIVE(addr) \
    asm volatile("mbarrier.arrive.shared.b64 _, [%0];" :: "r"((uint32_t)(addr)) : "memory")

#define MBARRIER_WAIT_PARITY(addr, parity) do {                                   \
    asm volatile(                                                                 \
        "{\n\t.reg .pred P1;\n\t"                                                 \
        "WAIT_LOOP_%=:\n\t"                                                       \
        "mbarrier.try_wait.parity.acquire.cta.shared::cta.b64 P1, [%0], %1, 0x989680;\n\t" \
        "@P1 bra.uni WAIT_DONE_%=;\n\t"                                           \
        "bra.uni WAIT_LOOP_%=;\n\t"                                               \
        "WAIT_DONE_%=:\n\t}"                                                      \
        :: "r"((uint32_t)(addr)), "r"((uint32_t)(parity)) : "memory");            \
} while (0)

#define MBAR_INVAL(addr) \
    asm volatile("mbarrier.inval.shared.b64 [%0];" :: "r"((uint32_t)(addr)) : "memory")

#define BULK_G2S(dst_smem, src_gmem, bytes, mbar)                                                   \
    asm volatile("cp.async.bulk.shared::cluster.global.mbarrier::complete_tx::bytes [%0], [%1], %2, [%3];" \
        :: "r"((uint32_t)(dst_smem)), "l"(src_gmem), "r"((uint32_t)(bytes)), "r"((uint32_t)(mbar)) : "memory")

DEVINL void ldsm_x4(uint32_t* r, uint32_t addr) {
    asm volatile("ldmatrix.sync.aligned.m8n8.x4.shared.b16 {%0,%1,%2,%3}, [%4];"
                 : "=r"(r[0]), "=r"(r[1]), "=r"(r[2]), "=r"(r[3]) : "r"(addr));
}

// fp16 MMA with fp16 accumulate: D(2 regs) = A(4) * B(2) + C(2)
DEVINL void mma_h(uint32_t* c, const uint32_t* a, uint32_t b0, uint32_t b1) {
    asm volatile(
        "mma.sync.aligned.m16n8k16.row.col.f16.f16.f16.f16 "
        "{%0,%1}, {%2,%3,%4,%5}, {%6,%7}, {%0,%1};"
        : "+r"(c[0]), "+r"(c[1])
        : "r"(a[0]), "r"(a[1]), "r"(a[2]), "r"(a[3]), "r"(b0), "r"(b1));
}

DEVINL float ex2f(float x) {
    float r;
    asm("ex2.approx.f32 %0, %1;" : "=f"(r) : "f"(x));
    return r;
}

// fp16 element (row 0..127, k 0..511) inside a 128-row tiled region:
// [k/64 superblock: 16KB][row/8 group: 1KB][SW128 atom: 8 rows x 128B]
DEVINL uint32_t sw_addr(uint32_t base, int row, int k) {
    return base + (uint32_t)(((k >> 6) << 14) + ((row >> 3) << 10) + ((row & 7) << 7)
                             + (((k & 63) << 1) ^ ((row & 7) << 4)));
}

// gmem scratch side (A): element (rr 0..127, k 0..511) in a 128x512 tile
DEVINL uint32_t tile_elem_off(int rr, int k) {
    return (uint32_t)(((k >> 6) << 14) + ((rr >> 3) << 10) + ((rr & 7) << 7)
                      + (((k & 63) << 1) ^ ((rr & 7) << 4)));
}

// ===================== prep =====================
DEVINL float dot4(float4 v) { return v.x * v.x + v.y * v.y + v.z * v.z + v.w * v.w; }
DEVINL uint32_t pk2h(float a, float b) {
    __half2 h = __floats2half2_rn(a, b);
    return *reinterpret_cast<uint32_t*>(&h);
}

__global__ void k_prep_a(const float* __restrict__ emb) {
    int r = blockIdx.x * 8 + (threadIdx.x >> 5);
    int lane = threadIdx.x & 31;
    unsigned char* base = g_A + (size_t)(r >> 7) * TILE_BYTES;
    int rr = r & 127;
    const float4* s = reinterpret_cast<const float4*>(emb + (size_t)r * EMB);
    float4 x0 = s[2 * lane], x1 = s[2 * lane + 1];
    float4 x2 = s[64 + 2 * lane], x3 = s[65 + 2 * lane];
    float ss = dot4(x0) + dot4(x1) + dot4(x2) + dot4(x3);
    #pragma unroll
    for (int o = 16; o; o >>= 1) ss += __shfl_xor_sync(0xFFFFFFFFu, ss, o);
    float inv = 1.0f / fmaxf(sqrtf(ss), 1e-12f);
    uint4 a, b;
    a.x = pk2h(x0.x * inv, x0.y * inv); a.y = pk2h(x0.z * inv, x0.w * inv);
    a.z = pk2h(x1.x * inv, x1.y * inv); a.w = pk2h(x1.z * inv, x1.w * inv);
    b.x = pk2h(x2.x * inv, x2.y * inv); b.y = pk2h(x2.z * inv, x2.w * inv);
    b.z = pk2h(x3.x * inv, x3.y * inv); b.w = pk2h(x3.z * inv, x3.w * inv);
    *reinterpret_cast<uint4*>(base + tile_elem_off(rr, 8 * lane)) = a;
    *reinterpret_cast<uint4*>(base + tile_elem_off(rr, 256 + 8 * lane)) = b;
}

// labels: detect int64 vs int32 (odd 32-bit words all zero => int64), zero rowsum
__global__ void k_labels(const int* __restrict__ lw) {
    __shared__ int s64;
    int tid = threadIdx.x;
    if (tid == 0) s64 = 1;
    __syncthreads();
    if (tid < 64) {
        if (lw[2 * tid + 1] != 0) atomicExch(&s64, 0);
    }
    __syncthreads();
    int is64 = s64;
    for (int i = tid; i < BATCH; i += 256) {
        g_labels[i] = is64 ? lw[2 * i] : lw[i];
        g_rowsum[i] = 0.0f;
    }
}

// exact fp32 target logit per row: margined, added to rowsum (GEMM skips label col)
__global__ void k_fix(const float* __restrict__ emb, const float* __restrict__ w) {
    int wrp = (blockIdx.x * blockDim.x + threadIdx.x) >> 5;   // 0..1023
    int lane = threadIdx.x & 31;
    int lbl = g_labels[wrp];
    const float4* e4 = reinterpret_cast<const float4*>(emb + (size_t)wrp * EMB);
    const float4* w4 = reinterpret_cast<const float4*>(w + (size_t)lbl * EMB);
    float ee = 0.f, ww = 0.f, ew = 0.f;
    #pragma unroll
    for (int i = 0; i < 4; i++) {
        float4 a = e4[lane + 32 * i], b = w4[lane + 32 * i];
        ee += dot4(a); ww += dot4(b);
        ew += a.x * b.x + a.y * b.y + a.z * b.z + a.w * b.w;
    }
    #pragma unroll
    for (int o = 16; o; o >>= 1) {
        ee += __shfl_xor_sync(0xFFFFFFFFu, ee, o);
        ww += __shfl_xor_sync(0xFFFFFFFFu, ww, o);
        ew += __shfl_xor_sync(0xFFFFFFFFu, ew, o);
    }
    if (lane == 0) {
        float t = ew / (fmaxf(sqrtf(ee), 1e-12f) * fmaxf(sqrtf(ww), 1e-12f));
        t = fminf(fmaxf(t, -1.0f), 1.0f);
        t = fminf(fmaxf(t, -1.0f + 1e-7f), 1.0f - 1e-7f);
        float lg = (t * COS_M - sqrtf(fmaxf(1.0f - t * t, 0.0f)) * SIN_M) * SCALE_S;
        g_target[wrp] = lg;
        atomicAdd(&g_rowsum[wrp], __expf(lg - 64.0f));
    }
}

// ===================== fp16 GEMM + fused W-normalize + softmax-partial epilogue ===
// 288 threads: warps 0-7 compute (4 m-slices x 2 n-slices, warp tile 32x64),
// warp 8 = loader. B tile (128 classes x 512 k fp16 = 128 KB) SMEM-resident,
// built by the prologue (W read from DRAM exactly once, f32 -> normalized fp16).
// MMA accumulates in fp16, flushed to f32 every 128 k (4x per m-tile).
__global__ __launch_bounds__(288, 1) void k_gemm(const float* __restrict__ wraw) {
    extern __shared__ unsigned char smem[];
    uint32_t sb = smem_u32(smem);
    int tid = threadIdx.x, wid = tid >> 5, lane = tid & 31;

    const uint32_t MB_AL = sb + 32;   // full barriers [2]
    const uint32_t MB_AC = sb + 64;   // consumed barriers [2]
    const uint32_t A_OFF = 1024;      // 2 x 32KB chunk buffers
    const uint32_t B_OFF = 66560;     // 1024-aligned; +128KB => 197632 total

    if (tid == 0) {
        for (int i = 0; i < 2; i++) {
            MBARRIER_INIT(MB_AL + 16 * i, 1);
            MBARRIER_INIT(MB_AC + 16 * i, 8);
        }
    }
    __syncthreads();

    if (wid == 8) {
        if (lane == 0) {
            #pragma unroll
            for (int g = 0; g < 2; g++) {
                MBARRIER_EXPECT_TX(MB_AL + 16 * g, CHUNK_BYTES);
                BULK_G2S(sb + A_OFF + g * CHUNK_BYTES, g_A + (size_t)g * CHUNK_BYTES,
                         CHUNK_BYTES, MB_AL + 16 * g);
            }
            int ac_ph[2] = {0, 0};
            for (int g = 2; g < NCHUNKS; g++) {
                int buf = g & 1;
                MBARRIER_WAIT_PARITY(MB_AC + 16 * buf, ac_ph[buf]); ac_ph[buf] ^= 1;
                MBARRIER_EXPECT_TX(MB_AL + 16 * buf, CHUNK_BYTES);
                BULK_G2S(sb + A_OFF + buf * CHUNK_BYTES, g_A + (size_t)g * CHUNK_BYTES,
                         CHUNK_BYTES, MB_AL + 16 * buf);
            }
        }
    } else {
        // ---- prologue: normalize this CTA's 128 W rows into SMEM B tile (fp16) ----
        #pragma unroll 1
        for (int rb = 0; rb < 4; rb++) {
            int r0 = wid * 16 + rb * 4;
            float4 x[4][4];
            #pragma unroll
            for (int rr = 0; rr < 4; rr++) {
                int c = blockIdx.x * NT + r0 + rr;
                if (c < NCLS) {
                    const float4* s = reinterpret_cast<const float4*>(wraw + (size_t)c * EMB);
                    #pragma unroll
                    for (int q = 0; q < 4; q++) x[rr][q] = s[q * 32 + lane];  // coalesced
                } else {
                    #pragma unroll
                    for (int q = 0; q < 4; q++) x[rr][q] = make_float4(0.f, 0.f, 0.f, 0.f);
                }
            }
            #pragma unroll
            for (int rr = 0; rr < 4; rr++) {
                float ss = dot4(x[rr][0]) + dot4(x[rr][1]) + dot4(x[rr][2]) + dot4(x[rr][3]);
                #pragma unroll
                for (int o = 16; o; o >>= 1) ss += __shfl_xor_sync(0xFFFFFFFFu, ss, o);
                float inv = 1.0f / fmaxf(sqrtf(ss), 1e-12f);
                #pragma unroll
                for (int q = 0; q < 4; q++) {
                    uint32_t lo = pk2h(x[rr][q].x * inv, x[rr][q].y * inv);
                    uint32_t hi = pk2h(x[rr][q].z * inv, x[rr][q].w * inv);
                    uint32_t addr = sw_addr(sb + B_OFF, r0 + rr, q * 128 + lane * 4);
                    asm volatile("st.shared.v2.b32 [%0], {%1, %2};" :: "r"(addr), "r"(lo), "r"(hi) : "memory");
                }
            }
        }
        asm volatile("bar.sync 1, 256;" ::: "memory");   // compute warps only

        // ---- main loop ----
        int wm = wid & 3, wn = wid >> 2;                 // 4 m-slices x 2 n-slices
        int grp = lane >> 3, r8 = lane & 7;
        int a_row = wm * 32 + ((grp & 1) << 3) + r8;
        int a_kof = (grp >> 1) << 3;
        int b_n   = wn * 64 + ((grp >> 1) << 3) + r8;
        int b_kof = (grp & 1) << 3;
        int qr = lane >> 2, ql = lane & 3;
        int cbase = blockIdx.x * NT + wn * 64 + ql * 2;

        int al_ph[2] = {0, 0};
        #pragma unroll 1
        for (int m = 0; m < 8; m++) {
            float accf[2][8][4];
            #pragma unroll
            for (int i = 0; i < 2; i++)
                #pragma unroll
                for (int j = 0; j < 8; j++)
                    #pragma unroll
                    for (int e = 0; e < 4; e++) accf[i][j][e] = 0.0f;

            #pragma unroll 1
            for (int kc = 0; kc < 4; kc++) {
                int g = m * 4 + kc, buf = g & 1;
                MBARRIER_WAIT_PARITY(MB_AL + 16 * buf, al_ph[buf]); al_ph[buf] ^= 1;
                uint32_t abuf = sb + A_OFF + buf * CHUNK_BYTES;

                uint32_t acch[2][8][2];
                #pragma unroll
                for (int i = 0; i < 2; i++)
                    #pragma unroll
                    for (int j = 0; j < 8; j++)
                        acch[i][j][0] = acch[i][j][1] = 0u;

                #pragma unroll
                for (int ks = 0; ks < 8; ks++) {
                    int k = ks * 16;
                    uint32_t a[2][4], b[4][4];
                    ldsm_x4(a[0], sw_addr(abuf, a_row,      k + a_kof));
                    ldsm_x4(a[1], sw_addr(abuf, a_row + 16, k + a_kof));
                    #pragma unroll
                    for (int jj = 0; jj < 4; jj++)
                        ldsm_x4(b[jj], sw_addr(sb + B_OFF, b_n + jj * 16, kc * 128 + k + b_kof));
                    if (ks == 7 && lane == 0) MBARRIER_ARRIVE(MB_AC + 16 * buf);
                    #pragma unroll
                    for (int i = 0; i < 2; i++)
                        #pragma unroll
                        for (int j = 0; j < 8; j++)
                            mma_h(acch[i][j], a[i],
                                  b[j >> 1][(j & 1) * 2], b[j >> 1][(j & 1) * 2 + 1]);
                }

                // flush fp16 accumulators into f32 (every 128 k)
                #pragma unroll
                for (int i = 0; i < 2; i++)
                    #pragma unroll
                    for (int j = 0; j < 8; j++) {
                        float2 lo = __half22float2(*reinterpret_cast<__half2*>(&acch[i][j][0]));
                        float2 hi = __half22float2(*reinterpret_cast<__half2*>(&acch[i][j][1]));
                        accf[i][j][0] += lo.x; accf[i][j][1] += lo.y;
                        accf[i][j][2] += hi.x; accf[i][j][3] += hi.y;
                    }
            }

            // fused epilogue: exp2(min(v*K, K) - K), label handled exactly by k_fix
            #pragma unroll
            for (int i = 0; i < 2; i++) {
                #pragma unroll
                for (int h = 0; h < 2; h++) {
                    int R = m * 128 + wm * 32 + i * 16 + h * 8 + qr;
                    int lbl = g_labels[R];
                    float sum = 0.0f;
                    #pragma unroll
                    for (int j = 0; j < 8; j++) {
                        #pragma unroll
                        for (int e = 0; e < 2; e++) {
                            int c = cbase + j * 8 + e;
                            float v = accf[i][j][h * 2 + e];
                            float x = ex2f(fminf(v * K_LOG2E, K_LOG2E) - K_LOG2E);
                            if (c != lbl) sum += x;
                        }
                    }
                    sum += __shfl_xor_sync(0xFFFFFFFFu, sum, 1);
                    sum += __shfl_xor_sync(0xFFFFFFFFu, sum, 2);
                    if (ql == 0) atomicAdd(&g_rowsum[R], sum);
                }
            }
        }
    }

    __syncthreads();
    if (tid == 0) {
        for (int i = 0; i < 2; i++) { MBAR_INVAL(MB_AL + 16 * i); MBAR_INVAL(MB_AC + 16 * i); }
    }
}

// ===================== final reduction =====================
__global__ void k_final(float* __restrict__ out) {
    __shared__ float sd[BATCH];
    int t = threadIdx.x;
    sd[t] = 64.0f + logf(g_rowsum[t]) - g_target[t];
    __syncthreads();
    for (int s = 512; s > 0; s >>= 1) {
        if (t < s) sd[t] += sd[t + s];
        __syncthreads();
    }
    if (t == 0) out[0] = sd[0] * (1.0f / (float)BATCH);
}

// ===================== launch =====================
extern "C" void kernel_launch(void* const* d_in, const int* in_sizes, int n_in,
                              void* d_out, int out_size) {
    const float* emb = (const float*)d_in[0];
    const float* w   = (const float*)d_in[1];
    const int*   lw  = (const int*)d_in[2];
    float* out = (float*)d_out;

    cudaFuncSetAttribute(k_gemm, cudaFuncAttributeMaxDynamicSharedMemorySize, 197632);

    k_labels<<<1, 256>>>(lw);
    k_prep_a<<<BATCH / 8, 256>>>(emb);
    k_fix<<<BATCH / 8, 256>>>(emb, w);
    k_gemm<<<NTILES, 288, 197632>>>(w);
    k_final<<<1, BATCH>>>(out);
}